// round 3
// baseline (speedup 1.0000x reference)
#include <cuda_runtime.h>
#include <cstdint>

// HistogramOfFeaturesModel on GB300.
// x:[B,16384] f32, W:[64,257] f32, b:[64] f32 -> out:[B,64] f32
//
// feats = [counts/16384 (128), boundaries (129)], out = feats @ W^T + b
// boundaries_j = mn + (j/128)*width  =>  boundary part of the GEMM collapses to
//   mn*S0[o] + width*S1[o],  S0[o]=sum_j W[o,128+j],  S1[o]=sum_j W[o,128+j]*(j/128)
//
// Persistent grid (2 CTAs/SM), one row at a time per CTA:
//   pass1: stream row (DRAM), min/max, warm L1
//   pass2: re-read row (L1/L2), bin into per-THREAD u8 histograms (no atomics),
//          XOR-swizzled so the SMEM crossbar sees no bank conflicts
//   merge: dp4a byte-sum, then 128x64 dot from SMEM-resident W columns.

#define NF    16384
#define NBINS 128
#define NOUT  64
#define TPB   256

__global__ __launch_bounds__(TPB) void hist_feats_kernel(
    const float* __restrict__ x,
    const float* __restrict__ W,
    const float* __restrict__ bias,
    float* __restrict__ out,
    int nrows)
{
    // 32 KB per-thread u8 histograms, swizzled: byte = bin*256 + (tid ^ ((bin&63)<<2))
    __shared__ unsigned char hist[NBINS * TPB];
    // count-columns of W, transposed + padded to 96 floats/row (48 KB; padding also
    // caps occupancy at 2 CTAs/SM so pass-2 L1 reuse survives)
    __shared__ float Wc[NBINS * 96];
    __shared__ float S0[NOUT], S1[NOUT], Bs[NOUT];
    __shared__ float countsf[NBINS];
    __shared__ float part[4][NOUT];
    __shared__ float wredmin[8], wredmax[8];

    const int tid = threadIdx.x;

    // ---------------- once per CTA: decompose W ----------------
    if (tid < NOUT) { S0[tid] = 0.f; S1[tid] = 0.f; Bs[tid] = bias[tid]; }
    __syncthreads();
    for (int e = tid; e < NOUT * 257; e += TPB) {
        float w = W[e];               // coalesced
        int o = e / 257;
        int i = e - o * 257;
        if (i < NBINS) {
            Wc[i * 96 + o] = w;
        } else {
            int j = i - NBINS;        // 0..128
            atomicAdd(&S0[o], w);                         // init-only, cheap
            atomicAdd(&S1[o], w * ((float)j * 0.0078125f)); // t_j = j/128 exact
        }
    }
    __syncthreads();

    for (int row = blockIdx.x; row < nrows; row += gridDim.x) {
        const float4* __restrict__ xr =
            reinterpret_cast<const float4*>(x + (size_t)row * NF);

        // zero histograms (8192 words, STS.128)
        {
            uint4 z = make_uint4(0u, 0u, 0u, 0u);
            uint4* h4 = reinterpret_cast<uint4*>(hist);
            #pragma unroll
            for (int k = 0; k < 8; k++) h4[k * TPB + tid] = z;
        }

        // -------- pass 1: min/max (streams row from DRAM, warms L1) --------
        float lmin = 3.402823466e38f, lmax = -3.402823466e38f;
        #pragma unroll 8
        for (int j = 0; j < 16; j++) {
            float4 v = xr[j * TPB + tid];
            lmin = fminf(lmin, fminf(fminf(v.x, v.y), fminf(v.z, v.w)));
            lmax = fmaxf(lmax, fmaxf(fmaxf(v.x, v.y), fmaxf(v.z, v.w)));
        }
        #pragma unroll
        for (int off = 16; off > 0; off >>= 1) {
            lmin = fminf(lmin, __shfl_xor_sync(0xffffffffu, lmin, off));
            lmax = fmaxf(lmax, __shfl_xor_sync(0xffffffffu, lmax, off));
        }
        if ((tid & 31) == 0) { wredmin[tid >> 5] = lmin; wredmax[tid >> 5] = lmax; }
        __syncthreads();                                   // S1

        // every thread reduces the 8 warp partials (broadcast LDS; cheaper than a sync)
        float mn = wredmin[0], mx = wredmax[0];
        #pragma unroll
        for (int k = 1; k < 8; k++) {
            mn = fminf(mn, wredmin[k]);
            mx = fmaxf(mx, wredmax[k]);
        }
        float width = mx - mn;
        float s = 128.f / ((width == 0.f) ? 1.f : width);  // mirrors reference guard

        // -------- pass 2: bin (row re-read hits L1/L2; per-thread u8 counters) -----
        #pragma unroll 4
        for (int j = 0; j < 16; j++) {
            float4 v = xr[j * TPB + tid];
            // (v-mn) >= 0 always; only the top clamp is needed (v==mx can round to 128)
            int b0 = __float2int_rd(fminf((v.x - mn) * s, 127.f));
            hist[b0 * TPB + (tid ^ ((b0 & 63) << 2))]++;
            int b1 = __float2int_rd(fminf((v.y - mn) * s, 127.f));
            hist[b1 * TPB + (tid ^ ((b1 & 63) << 2))]++;
            int b2 = __float2int_rd(fminf((v.z - mn) * s, 127.f));
            hist[b2 * TPB + (tid ^ ((b2 & 63) << 2))]++;
            int b3 = __float2int_rd(fminf((v.w - mn) * s, 127.f));
            hist[b3 * TPB + (tid ^ ((b3 & 63) << 2))]++;
        }
        __syncthreads();                                   // S2

        // -------- merge: 2 threads per bin, dp4a over packed u8 counters --------
        {
            int bin = tid >> 1;
            int h   = tid & 1;
            const unsigned int* hw = reinterpret_cast<const unsigned int*>(hist);
            unsigned int acc = 0;
            int base = bin * (TPB / 4);     // 64 words per bin row
            int msk  = bin & 63;            // word-level swizzle = byte swizzle >> 2
            #pragma unroll 8
            for (int m = h * 32; m < h * 32 + 32; m++) {
                acc = __dp4a(hw[base + (m ^ msk)], 0x01010101u, acc);
            }
            acc += __shfl_xor_sync(0xffffffffu, acc, 1);
            if (h == 0) countsf[bin] = (float)acc * (1.f / 16384.f);
        }
        __syncthreads();                                   // S3

        // -------- epilogue: out[o] = counts.Wc[:,o] + mn*S0 + width*S1 + b --------
        {
            int o = tid & 63;
            int g = tid >> 6;
            float acc = 0.f;
            int ibase = g * 32;
            #pragma unroll 8
            for (int i = 0; i < 32; i++) {
                acc += countsf[ibase + i] * Wc[(ibase + i) * 96 + o];
            }
            part[g][o] = acc;
        }
        __syncthreads();                                   // S4
        if (tid < NOUT) {
            float r = part[0][tid] + part[1][tid] + part[2][tid] + part[3][tid];
            r += mn * S0[tid] + width * S1[tid] + Bs[tid];
            out[(size_t)row * NOUT + tid] = r;
        }
        // next-iteration hist zeroing only conflicts with this row's merge reads,
        // which completed before S3 — no extra sync needed.
    }
}

extern "C" void kernel_launch(void* const* d_in, const int* in_sizes, int n_in,
                              void* d_out, int out_size) {
    const float* x = (const float*)d_in[0];
    const float* W = (const float*)d_in[1];
    const float* b = (const float*)d_in[2];
    float* out = (float*)d_out;
    int nrows = in_sizes[0] / NF;
    int grid = 296;                 // 2 CTAs per SM on 148 SMs, persistent
    if (grid > nrows) grid = nrows;
    hist_feats_kernel<<<grid, TPB>>>(x, W, b, out, nrows);
}

// round 6
// speedup vs baseline: 2.8523x; 2.8523x over previous
#include <cuda_runtime.h>
#include <cstdint>

// HistogramOfFeaturesModel on GB300 — R5 (resubmit of R4: occupancy 2->6 CTAs/SM).
// x:[B,16384] f32, W:[64,257] f32, b:[64] f32 -> out:[B,64] f32
//
// feats = [counts/16384 (128), boundaries (129)], out = feats @ W^T + b
// boundary half collapses analytically: mn*S0[o] + width*S1[o].
//
// prep_kernel (once per launch): Wt[i*64+o] = W[o*257+i], S0/S1 reductions.
// hist_feats_kernel: persistent, 6 CTAs/SM (SMEM 33.7KB), one row per iter:
//   pass1 DRAM stream -> min/max; pass2 L2 re-read -> per-THREAD u8 histograms
//   (no atomics, XOR-swizzled banks); dp4a merge; 128x64 dot vs global Wt.

#define NF    16384
#define NBINS 128
#define NOUT  64
#define TPB   256

__device__ float g_Wt[NBINS * NOUT];   // [i][o], o contiguous -> coalesced
__device__ float g_S0[NOUT];
__device__ float g_S1[NOUT];

__global__ void prep_kernel(const float* __restrict__ W) {
    const int tid = threadIdx.x;
    // transpose count-columns of W
    for (int e = tid; e < NBINS * NOUT; e += TPB) {
        int i = e >> 6;          // 0..127
        int o = e & 63;
        g_Wt[e] = W[o * 257 + i];
    }
    // boundary-part reductions: 2 threads per output o
    if (tid < 128) {
        int o = tid >> 1;
        int h = tid & 1;
        float s0 = 0.f, s1 = 0.f;
        for (int j = h; j <= 128; j += 2) {
            float w = W[o * 257 + 128 + j];
            s0 += w;
            s1 += w * ((float)j * 0.0078125f);   // t_j = j/128 exact
        }
        s0 += __shfl_xor_sync(0xffffffffu, s0, 1);
        s1 += __shfl_xor_sync(0xffffffffu, s1, 1);
        if (h == 0) { g_S0[o] = s0; g_S1[o] = s1; }
    }
}

__global__ __launch_bounds__(TPB, 6) void hist_feats_kernel(
    const float* __restrict__ x,
    const float* __restrict__ bias,
    float* __restrict__ out,
    int nrows)
{
    // 32 KB per-thread u8 histograms: byte = (bin<<8) | (tid ^ ((bin&63)<<2))
    __shared__ unsigned char hist[NBINS * TPB];
    __shared__ float S0[NOUT], S1[NOUT], Bs[NOUT];
    __shared__ float countsf[NBINS];
    __shared__ float part[4][NOUT];
    __shared__ float wredmin[8], wredmax[8];

    const int tid = threadIdx.x;

    if (tid < NOUT) {
        S0[tid] = g_S0[tid];
        S1[tid] = g_S1[tid];
        Bs[tid] = bias[tid];
    }
    __syncthreads();

    for (int row = blockIdx.x; row < nrows; row += gridDim.x) {
        const float4* __restrict__ xr =
            reinterpret_cast<const float4*>(x + (size_t)row * NF);

        // zero histograms (8192 words via STS.128)
        {
            uint4 z = make_uint4(0u, 0u, 0u, 0u);
            uint4* h4 = reinterpret_cast<uint4*>(hist);
            #pragma unroll
            for (int k = 0; k < 8; k++) h4[k * TPB + tid] = z;
        }

        // -------- pass 1: min/max (streams row from DRAM) --------
        float lmin = 3.402823466e38f, lmax = -3.402823466e38f;
        #pragma unroll 4
        for (int j = 0; j < 16; j++) {
            float4 v = xr[j * TPB + tid];
            lmin = fminf(lmin, fminf(fminf(v.x, v.y), fminf(v.z, v.w)));
            lmax = fmaxf(lmax, fmaxf(fmaxf(v.x, v.y), fmaxf(v.z, v.w)));
        }
        #pragma unroll
        for (int off = 16; off > 0; off >>= 1) {
            lmin = fminf(lmin, __shfl_xor_sync(0xffffffffu, lmin, off));
            lmax = fmaxf(lmax, __shfl_xor_sync(0xffffffffu, lmax, off));
        }
        if ((tid & 31) == 0) { wredmin[tid >> 5] = lmin; wredmax[tid >> 5] = lmax; }
        __syncthreads();                                   // S1

        float mn = wredmin[0], mx = wredmax[0];
        #pragma unroll
        for (int k = 1; k < 8; k++) {
            mn = fminf(mn, wredmin[k]);
            mx = fmaxf(mx, wredmax[k]);
        }
        float width = mx - mn;
        float s   = 128.f / ((width == 0.f) ? 1.f : width);  // mirrors reference guard
        float off = -mn * s;                                 // bin = floor(fma(v,s,off))

        // -------- pass 2: bin (re-read hits L2; per-thread u8 counters) --------
        #pragma unroll 2
        for (int j = 0; j < 16; j++) {
            float4 v = xr[j * TPB + tid];
            // fma(v,s,off) >= ~0; top clamp needed (v==mx can hit 128)
            int b0 = __float2int_rd(fminf(fmaf(v.x, s, off), 127.f));
            int b1 = __float2int_rd(fminf(fmaf(v.y, s, off), 127.f));
            int b2 = __float2int_rd(fminf(fmaf(v.z, s, off), 127.f));
            int b3 = __float2int_rd(fminf(fmaf(v.w, s, off), 127.f));
            b0 = max(b0, 0); b1 = max(b1, 0); b2 = max(b2, 0); b3 = max(b3, 0);
            int a0 = (b0 << 8) | (tid ^ ((b0 & 63) << 2));
            int a1 = (b1 << 8) | (tid ^ ((b1 & 63) << 2));
            int a2 = (b2 << 8) | (tid ^ ((b2 & 63) << 2));
            int a3 = (b3 << 8) | (tid ^ ((b3 & 63) << 2));
            hist[a0]++;
            hist[a1]++;
            hist[a2]++;
            hist[a3]++;
        }
        __syncthreads();                                   // S2

        // -------- merge: 2 threads per bin, dp4a over packed u8 counters --------
        {
            int bin = tid >> 1;
            int h   = tid & 1;
            const unsigned int* hw = reinterpret_cast<const unsigned int*>(hist);
            unsigned int acc = 0;
            int base = bin * (TPB / 4);     // 64 words per bin row
            int msk  = bin & 63;            // word-level swizzle = byte swizzle >> 2
            #pragma unroll 8
            for (int m = h * 32; m < h * 32 + 32; m++) {
                acc = __dp4a(hw[base + (m ^ msk)], 0x01010101u, acc);
            }
            acc += __shfl_xor_sync(0xffffffffu, acc, 1);
            if (h == 0) countsf[bin] = (float)acc * (1.f / 16384.f);
        }
        __syncthreads();                                   // S3

        // -------- epilogue: out[o] = counts.Wt[:,o] + mn*S0 + width*S1 + b ------
        {
            int o = tid & 63;
            int g = tid >> 6;
            float acc = 0.f;
            int ib = g * 32;
            #pragma unroll 8
            for (int i = 0; i < 32; i++) {
                acc += countsf[ib + i] * g_Wt[(ib + i) * NOUT + o];  // coalesced
            }
            part[g][o] = acc;
        }
        __syncthreads();                                   // S4
        if (tid < NOUT) {
            float r = part[0][tid] + part[1][tid] + part[2][tid] + part[3][tid];
            r += mn * S0[tid] + width * S1[tid] + Bs[tid];
            out[(size_t)row * NOUT + tid] = r;
        }
        // next-iteration hist zeroing is ordered behind this row's merge reads
        // by the S3/S4 barriers -> no extra sync needed.
    }
}

extern "C" void kernel_launch(void* const* d_in, const int* in_sizes, int n_in,
                              void* d_out, int out_size) {
    const float* x = (const float*)d_in[0];
    const float* W = (const float*)d_in[1];
    const float* b = (const float*)d_in[2];
    float* out = (float*)d_out;
    int nrows = in_sizes[0] / NF;

    prep_kernel<<<1, TPB>>>(W);

    int grid = 6 * 148;             // 6 CTAs per SM, persistent
    if (grid > nrows) grid = nrows;
    hist_feats_kernel<<<grid, TPB>>>(x, b, out, nrows);
}

// round 8
// speedup vs baseline: 3.3060x; 1.1591x over previous
#include <cuda_runtime.h>
#include <cstdint>

// HistogramOfFeaturesModel on GB300 — R6: conflict-free per-lane-bank histogram.
// x:[B,16384] f32, W:[64,257] f32, b:[64] f32 -> out:[B,64] f32
//
// R5 ncu: L1=76% — byte-RMW binning had ~3.3-way random bank conflicts.
// New layout: counter(w,l,b) at byte  w*4096 + (b>>2)*128 + l*4 + (b&3)
//   -> bank = l for every access, conflict-free for ANY bin distribution.
// Per-warp merge (own region only, __syncwarp, no block barrier):
//   lane l owns bins 4l..4l+3; vadd4 pairs (<=128, safe) + dp4a byte extract.

#define NF    16384
#define NBINS 128
#define NOUT  64
#define TPB   256

__device__ float g_Wt[NBINS * NOUT];   // [i][o], o contiguous -> coalesced
__device__ float g_S0[NOUT];
__device__ float g_S1[NOUT];

__global__ void prep_kernel(const float* __restrict__ W) {
    const int tid = threadIdx.x;
    for (int e = tid; e < NBINS * NOUT; e += TPB) {
        int i = e >> 6;
        int o = e & 63;
        g_Wt[e] = W[o * 257 + i];
    }
    if (tid < 128) {
        int o = tid >> 1;
        int h = tid & 1;
        float s0 = 0.f, s1 = 0.f;
        for (int j = h; j <= 128; j += 2) {
            float w = W[o * 257 + 128 + j];
            s0 += w;
            s1 += w * ((float)j * 0.0078125f);   // t_j = j/128 exact
        }
        s0 += __shfl_xor_sync(0xffffffffu, s0, 1);
        s1 += __shfl_xor_sync(0xffffffffu, s1, 1);
        if (h == 0) { g_S0[o] = s0; g_S1[o] = s1; }
    }
}

__global__ __launch_bounds__(TPB, 6) void hist_feats_kernel(
    const float* __restrict__ x,
    const float* __restrict__ bias,
    float* __restrict__ out,
    int nrows)
{
    __shared__ unsigned int hist32[8 * 1024];   // 32 KB: [warp][(b>>2)*32 + lane]
    __shared__ unsigned int stage[8 * 128];     // 4 KB; aliased as part[] after S3
    __shared__ float countsf[NBINS];
    __shared__ float S0[NOUT], S1[NOUT], Bs[NOUT];
    __shared__ float wredmin[8], wredmax[8];

    unsigned char* hist8 = reinterpret_cast<unsigned char*>(hist32);
    float* part = reinterpret_cast<float*>(stage);

    const int tid = threadIdx.x;
    const int w   = tid >> 5;
    const int l   = tid & 31;
    const int hbase = (w << 12) | (l << 2);     // byte base; bank(l) always

    if (tid < NOUT) {
        S0[tid] = g_S0[tid];
        S1[tid] = g_S1[tid];
        Bs[tid] = bias[tid];
    }
    __syncthreads();

    for (int row = blockIdx.x; row < nrows; row += gridDim.x) {
        const float4* __restrict__ xr =
            reinterpret_cast<const float4*>(x + (size_t)row * NF);

        // zero this warp's own 4KB region (no cross-warp hazard)
        {
            uint4 z = make_uint4(0u, 0u, 0u, 0u);
            uint4* h4 = reinterpret_cast<uint4*>(hist8 + (w << 12));
            #pragma unroll
            for (int k = 0; k < 8; k++) h4[(k << 5) + l] = z;
        }

        // -------- pass 1: min/max (streams row from DRAM) --------
        float lmin = 3.402823466e38f, lmax = -3.402823466e38f;
        #pragma unroll 4
        for (int j = 0; j < 16; j++) {
            float4 v = xr[j * TPB + tid];
            lmin = fminf(lmin, fminf(fminf(v.x, v.y), fminf(v.z, v.w)));
            lmax = fmaxf(lmax, fmaxf(fmaxf(v.x, v.y), fmaxf(v.z, v.w)));
        }
        #pragma unroll
        for (int off = 16; off > 0; off >>= 1) {
            lmin = fminf(lmin, __shfl_xor_sync(0xffffffffu, lmin, off));
            lmax = fmaxf(lmax, __shfl_xor_sync(0xffffffffu, lmax, off));
        }
        if (l == 0) { wredmin[w] = lmin; wredmax[w] = lmax; }
        __syncthreads();                                   // S1 (also orders zeroing)

        float mn = wredmin[0], mx = wredmax[0];
        #pragma unroll
        for (int k = 1; k < 8; k++) {
            mn = fminf(mn, wredmin[k]);
            mx = fmaxf(mx, wredmax[k]);
        }
        float width = mx - mn;
        float s   = 128.f / ((width == 0.f) ? 1.f : width);  // mirrors reference guard
        float off = -mn * s;                                 // bin = floor(fma(v,s,off))

        // -------- pass 2: bin (conflict-free per-lane-bank u8 counters) --------
        #pragma unroll 2
        for (int j = 0; j < 16; j++) {
            float4 v = xr[j * TPB + tid];
            int b0 = __float2int_rd(fminf(fmaf(v.x, s, off), 127.f));
            int b1 = __float2int_rd(fminf(fmaf(v.y, s, off), 127.f));
            int b2 = __float2int_rd(fminf(fmaf(v.z, s, off), 127.f));
            int b3 = __float2int_rd(fminf(fmaf(v.w, s, off), 127.f));
            b0 = max(b0, 0); b1 = max(b1, 0); b2 = max(b2, 0); b3 = max(b3, 0);
            // byte offset: ((b>>2)<<7) | (b&3) == ((b&124)<<5) | (b&3)
            hist8[hbase + (((b0 & 124) << 5) | (b0 & 3))]++;
            hist8[hbase + (((b1 & 124) << 5) | (b1 & 3))]++;
            hist8[hbase + (((b2 & 124) << 5) | (b2 & 3))]++;
            hist8[hbase + (((b3 & 124) << 5) | (b3 & 3))]++;
        }
        __syncwarp();   // warp-local: region written only by this warp

        // -------- per-warp merge: lane l -> bins 4l..4l+3 of warp w --------
        {
            const unsigned int* hw = hist32 + (w << 10) + (l << 5);
            unsigned int a0 = 0, a1 = 0, a2 = 0, a3 = 0;
            #pragma unroll
            for (int j = 0; j < 32; j += 2) {
                // column order c = l^j: bank c, distinct per lane -> conflict-free
                unsigned int p = __vadd4(hw[l ^ j], hw[l ^ (j + 1)]);  // bytes <= 128
                a0 = __dp4a(p, 0x00000001u, a0);
                a1 = __dp4a(p, 0x00000100u, a1);
                a2 = __dp4a(p, 0x00010000u, a2);
                a3 = __dp4a(p, 0x01000000u, a3);
            }
            *reinterpret_cast<uint4*>(&stage[(w << 7) + (l << 2)]) =
                make_uint4(a0, a1, a2, a3);
        }
        __syncthreads();                                   // S2

        // cross-warp reduce -> normalized counts
        float mnv = mn, wdv = width;   // keep live across barriers
        if (tid < NBINS) {
            unsigned int c = 0;
            #pragma unroll
            for (int ww = 0; ww < 8; ww++) c += stage[(ww << 7) + tid];
            countsf[tid] = (float)c * (1.f / 16384.f);
        }
        __syncthreads();                                   // S3

        // -------- epilogue: out[o] = counts.Wt[:,o] + mn*S0 + width*S1 + b ------
        {
            int o = tid & 63;
            int g = tid >> 6;
            float acc = 0.f;
            int ib = g * 32;
            #pragma unroll 8
            for (int i = 0; i < 32; i++) {
                acc += countsf[ib + i] * g_Wt[(ib + i) * NOUT + o];  // coalesced
            }
            part[(g << 6) + o] = acc;    // aliases stage; stage readers done at S3
        }
        __syncthreads();                                   // S4
        if (tid < NOUT) {
            float r = part[tid] + part[64 + tid] + part[128 + tid] + part[192 + tid];
            r += mnv * S0[tid] + wdv * S1[tid] + Bs[tid];
            out[(size_t)row * NOUT + tid] = r;
        }
        // next row's zeroing touches only this warp's region and is ordered
        // behind this row's merge (same warp) and S4.
    }
}

extern "C" void kernel_launch(void* const* d_in, const int* in_sizes, int n_in,
                              void* d_out, int out_size) {
    const float* x = (const float*)d_in[0];
    const float* W = (const float*)d_in[1];
    const float* b = (const float*)d_in[2];
    float* out = (float*)d_out;
    int nrows = in_sizes[0] / NF;

    prep_kernel<<<1, TPB>>>(W);

    int grid = 6 * 148;             // 6 CTAs per SM, persistent
    if (grid > nrows) grid = nrows;
    hist_feats_kernel<<<grid, TPB>>>(x, b, out, nrows);
}